// round 2
// baseline (speedup 1.0000x reference)
#include <cuda_runtime.h>
#include <math.h>

#define BB 64
#define SS 512
#define HH 1024
#define II 1024
#define CC 64            // chunk length
#define NCH (SS/CC)      // 8 chunks
#define LRI (0.01f/1024.0f)
#define EPSF 1e-5f

// ---------------- device state (no allocation allowed) ----------------
__device__ float g_W[(size_t)BB*HH*II];   // 256 MB fast weights
__device__ float g_bst[BB*II];            // fast bias
__device__ float g_tgt[(size_t)BB*SS*II]; // 128 MB precomputed targets
__device__ float g_base[BB*CC*II];        // x_chunk @ W_{t0}
__device__ float g_err[BB*CC*II];         // chunk errs (consumed by next wpass)
__device__ float g_act[BB*CC*II];         // silu(inner)
__device__ float g_ttt[BB*CC*HH];         // silu(inner)@Wo + bo
__device__ float g_gate[BB*CC*HH];        // concat@Wg + bg (pre-sigmoid)
__device__ float g_G[BB*CC*CC];           // gram x_t.x_s per batch

// ---------------------------------------------------------------------
__global__ void k_init(const float* __restrict__ Wi, const float* __restrict__ bi) {
    size_t stride = (size_t)gridDim.x * blockDim.x;
    size_t t0 = (size_t)blockIdx.x * blockDim.x + threadIdx.x;
    const size_t NW = (size_t)BB * HH * II;
    for (size_t i = t0; i < NW; i += stride) g_W[i] = Wi[i & (HH*II - 1)];
    for (size_t i = t0; i < (size_t)BB*II; i += stride) g_bst[i] = bi[i & (II - 1)];
}

// ---------------------------------------------------------------------
// Gram: G[b][t][s] = x_{t0+t} . x_{t0+s}   (one block per batch)
// ---------------------------------------------------------------------
__global__ void k_gram(const float* __restrict__ x, int t0) {
    const int b = blockIdx.x, tid = threadIdx.x;
    const int tq = tid >> 4, tr = tid & 15;   // thread tile 4t x 4s
    __shared__ float Xs[64][33];
    float acc[4][4];
    #pragma unroll
    for (int i = 0; i < 4; ++i)
        #pragma unroll
        for (int j = 0; j < 4; ++j) acc[i][j] = 0.f;

    for (int h0 = 0; h0 < HH; h0 += 32) {
        int r = tid >> 2, c = (tid & 3) * 8;
        const float* xr = &x[((size_t)b*SS + t0 + r)*HH + h0 + c];
        float4 v0 = *(const float4*)xr, v1 = *(const float4*)(xr + 4);
        Xs[r][c+0]=v0.x; Xs[r][c+1]=v0.y; Xs[r][c+2]=v0.z; Xs[r][c+3]=v0.w;
        Xs[r][c+4]=v1.x; Xs[r][c+5]=v1.y; Xs[r][c+6]=v1.z; Xs[r][c+7]=v1.w;
        __syncthreads();
        #pragma unroll 8
        for (int h = 0; h < 32; ++h) {
            float a0=Xs[tq*4+0][h], a1=Xs[tq*4+1][h], a2=Xs[tq*4+2][h], a3=Xs[tq*4+3][h];
            float b0=Xs[tr*4+0][h], b1=Xs[tr*4+1][h], b2=Xs[tr*4+2][h], b3=Xs[tr*4+3][h];
            acc[0][0]+=a0*b0; acc[0][1]+=a0*b1; acc[0][2]+=a0*b2; acc[0][3]+=a0*b3;
            acc[1][0]+=a1*b0; acc[1][1]+=a1*b1; acc[1][2]+=a1*b2; acc[1][3]+=a1*b3;
            acc[2][0]+=a2*b0; acc[2][1]+=a2*b1; acc[2][2]+=a2*b2; acc[2][3]+=a2*b3;
            acc[3][0]+=a3*b0; acc[3][1]+=a3*b1; acc[3][2]+=a3*b2; acc[3][3]+=a3*b3;
        }
        __syncthreads();
    }
    #pragma unroll
    for (int i = 0; i < 4; ++i)
        #pragma unroll
        for (int j = 0; j < 4; ++j)
            g_G[(b*CC + tq*4+i)*CC + tr*4+j] = acc[i][j];
}

// ---------------------------------------------------------------------
// Fused W pass: (optionally) W -= Xprev^T Eprev (rank-64), then
// base = Xc @ W  — one read+write pass over W per chunk.
// grid (I/128, B), 256 threads, dynamic smem 66560 B.
// ---------------------------------------------------------------------
__global__ void k_wpass(const float* __restrict__ x, int t0, int do_update) {
    extern __shared__ float sm[];
    float* Ep = sm;               // [64][128]  (LRI pre-folded)
    float* Xp = Ep + 64*128;      // [64][33]
    float* Xc = Xp + 64*33;       // [64][33]
    float* Wt = Xc + 64*33;       // [32][132]
    const int b = blockIdx.y, i0 = blockIdx.x * 128, tid = threadIdx.x;
    const int uh = tid >> 3, ui = (tid & 7) * 16;   // update-phase mapping
    const int tm = tid >> 4, tn = tid & 15;          // base-phase mapping

    if (do_update) {
        #pragma unroll
        for (int l = 0; l < 8; ++l) {
            int fl = tid + l*256;              // float4 index, 2048 total
            int s = fl >> 5, ii = (fl & 31) * 4;
            float4 e = *(const float4*)&g_err[((b<<6)+s)*II + i0 + ii];
            float* d = &Ep[s*128 + ii];
            d[0]=LRI*e.x; d[1]=LRI*e.y; d[2]=LRI*e.z; d[3]=LRI*e.w;
        }
    }

    float acc[4][8];
    #pragma unroll
    for (int i = 0; i < 4; ++i)
        #pragma unroll
        for (int j = 0; j < 8; ++j) acc[i][j] = 0.f;

    for (int h0 = 0; h0 < HH; h0 += 32) {
        {   // x tiles
            int r = tid >> 2, c = (tid & 3) * 8;
            const float* xr = &x[((size_t)b*SS + t0 + r)*HH + h0 + c];
            float4 v0 = *(const float4*)xr, v1 = *(const float4*)(xr+4);
            float* d = &Xc[r*33 + c];
            d[0]=v0.x; d[1]=v0.y; d[2]=v0.z; d[3]=v0.w;
            d[4]=v1.x; d[5]=v1.y; d[6]=v1.z; d[7]=v1.w;
            if (do_update) {
                const float* xpr = xr - (size_t)CC*HH;
                float4 p0 = *(const float4*)xpr, p1 = *(const float4*)(xpr+4);
                float* dp = &Xp[r*33 + c];
                dp[0]=p0.x; dp[1]=p0.y; dp[2]=p0.z; dp[3]=p0.w;
                dp[4]=p1.x; dp[5]=p1.y; dp[6]=p1.z; dp[7]=p1.w;
            }
        }
        float* wg = &g_W[(((size_t)b<<10) + (h0 + uh))*II + i0 + ui];
        float4 w0 = *(float4*)(wg+0), w1 = *(float4*)(wg+4);
        float4 w2 = *(float4*)(wg+8), w3 = *(float4*)(wg+12);

        __syncthreads();   // Xc/Xp ready
        if (do_update) {
            #pragma unroll 4
            for (int s = 0; s < 64; ++s) {
                float xv = Xp[s*33 + uh];
                const float* e = &Ep[s*128 + ui];
                float4 e0 = *(const float4*)(e+0), e1 = *(const float4*)(e+4);
                float4 e2 = *(const float4*)(e+8), e3 = *(const float4*)(e+12);
                w0.x-=xv*e0.x; w0.y-=xv*e0.y; w0.z-=xv*e0.z; w0.w-=xv*e0.w;
                w1.x-=xv*e1.x; w1.y-=xv*e1.y; w1.z-=xv*e1.z; w1.w-=xv*e1.w;
                w2.x-=xv*e2.x; w2.y-=xv*e2.y; w2.z-=xv*e2.z; w2.w-=xv*e2.w;
                w3.x-=xv*e3.x; w3.y-=xv*e3.y; w3.z-=xv*e3.z; w3.w-=xv*e3.w;
            }
            *(float4*)(wg+0)=w0; *(float4*)(wg+4)=w1;
            *(float4*)(wg+8)=w2; *(float4*)(wg+12)=w3;
        }
        {   // publish W tile to shared for base phase
            float* d = &Wt[uh*132 + ui];
            *(float4*)(d+0)=w0; *(float4*)(d+4)=w1;
            *(float4*)(d+8)=w2; *(float4*)(d+12)=w3;
        }
        __syncthreads();
        #pragma unroll 4
        for (int h = 0; h < 32; ++h) {
            float a0 = Xc[(tm*4+0)*33 + h], a1 = Xc[(tm*4+1)*33 + h];
            float a2 = Xc[(tm*4+2)*33 + h], a3 = Xc[(tm*4+3)*33 + h];
            const float* wr = &Wt[h*132 + tn*8];
            float4 b0 = *(const float4*)(wr+0), b1 = *(const float4*)(wr+4);
            acc[0][0]+=a0*b0.x; acc[0][1]+=a0*b0.y; acc[0][2]+=a0*b0.z; acc[0][3]+=a0*b0.w;
            acc[0][4]+=a0*b1.x; acc[0][5]+=a0*b1.y; acc[0][6]+=a0*b1.z; acc[0][7]+=a0*b1.w;
            acc[1][0]+=a1*b0.x; acc[1][1]+=a1*b0.y; acc[1][2]+=a1*b0.z; acc[1][3]+=a1*b0.w;
            acc[1][4]+=a1*b1.x; acc[1][5]+=a1*b1.y; acc[1][6]+=a1*b1.z; acc[1][7]+=a1*b1.w;
            acc[2][0]+=a2*b0.x; acc[2][1]+=a2*b0.y; acc[2][2]+=a2*b0.z; acc[2][3]+=a2*b0.w;
            acc[2][4]+=a2*b1.x; acc[2][5]+=a2*b1.y; acc[2][6]+=a2*b1.z; acc[2][7]+=a2*b1.w;
            acc[3][0]+=a3*b0.x; acc[3][1]+=a3*b0.y; acc[3][2]+=a3*b0.z; acc[3][3]+=a3*b0.w;
            acc[3][4]+=a3*b1.x; acc[3][5]+=a3*b1.y; acc[3][6]+=a3*b1.z; acc[3][7]+=a3*b1.w;
        }
        __syncthreads();
    }
    #pragma unroll
    for (int si = 0; si < 4; ++si) {
        float* d = &g_base[((b<<6) + tm*4 + si)*II + i0 + tn*8];
        *(float4*)(d+0) = make_float4(acc[si][0],acc[si][1],acc[si][2],acc[si][3]);
        *(float4*)(d+4) = make_float4(acc[si][4],acc[si][5],acc[si][6],acc[si][7]);
    }
}

// ---------------------------------------------------------------------
// Intra-chunk recurrence: parallel over (b,i); sequential over t in regs.
// ---------------------------------------------------------------------
__global__ void k_recur(int t0) {
    __shared__ float Gs[CC*CC];
    const int b = blockIdx.y;
    const int i = blockIdx.x * 256 + threadIdx.x;
    const int tid = threadIdx.x;
    #pragma unroll
    for (int l = 0; l < 16; ++l)
        Gs[tid + l*256] = LRI * (g_G[b*CC*CC + tid + l*256] + 1.0f);
    __syncthreads();

    float bstv = g_bst[b*II + i];
    float eh[CC];
    float sumerr = 0.f;
    #pragma unroll
    for (int t = 0; t < CC; ++t) {
        float inner = g_base[((b<<6)+t)*II + i] + bstv;
        #pragma unroll
        for (int s = 0; s < t; ++s) inner -= Gs[t*CC + s] * eh[s];
        float tg = g_tgt[((size_t)b*SS + t0 + t)*II + i];
        float e = inner - tg;
        eh[t] = e; sumerr += e;
        g_err[((b<<6)+t)*II + i] = e;
        g_act[((b<<6)+t)*II + i] = inner / (1.0f + expf(-inner));
    }
    g_bst[b*II + i] = bstv - LRI * sumerr;
}

// ---------------------------------------------------------------------
// Plain GEMM: C[M,1024] = A[M,K] @ Bw[K,1024] + bias. 128x128 tile, 256 thr.
// ---------------------------------------------------------------------
__global__ void k_gemm(const float* __restrict__ A, const float* __restrict__ Bw,
                       const float* __restrict__ bias, float* __restrict__ Cout,
                       int K) {
    __shared__ float As[8*132];
    __shared__ float Bs[8*128];
    const int m0 = blockIdx.y * 128, n0 = blockIdx.x * 128;
    const int tid = threadIdx.x, tx = tid & 15, ty = tid >> 4;
    float acc[8][8];
    #pragma unroll
    for (int i = 0; i < 8; ++i)
        #pragma unroll
        for (int j = 0; j < 8; ++j) acc[i][j] = 0.f;

    const int am = tid >> 1, ak = (tid & 1) * 4;
    const int bk = tid >> 5, bn = (tid & 31) * 4;

    for (int k0 = 0; k0 < K; k0 += 8) {
        float4 a = *(const float4*)&A[(size_t)(m0 + am)*K + k0 + ak];
        As[(ak+0)*132+am]=a.x; As[(ak+1)*132+am]=a.y;
        As[(ak+2)*132+am]=a.z; As[(ak+3)*132+am]=a.w;
        *(float4*)&Bs[bk*128 + bn] = *(const float4*)&Bw[(size_t)(k0+bk)*1024 + n0 + bn];
        __syncthreads();
        #pragma unroll
        for (int kk = 0; kk < 8; ++kk) {
            float4 a0 = *(const float4*)&As[kk*132 + ty*8];
            float4 a1 = *(const float4*)&As[kk*132 + ty*8 + 4];
            float4 b0 = *(const float4*)&Bs[kk*128 + tx*8];
            float4 b1 = *(const float4*)&Bs[kk*128 + tx*8 + 4];
            float ar[8] = {a0.x,a0.y,a0.z,a0.w,a1.x,a1.y,a1.z,a1.w};
            float br[8] = {b0.x,b0.y,b0.z,b0.w,b1.x,b1.y,b1.z,b1.w};
            #pragma unroll
            for (int i = 0; i < 8; ++i)
                #pragma unroll
                for (int j = 0; j < 8; ++j) acc[i][j] += ar[i]*br[j];
        }
        __syncthreads();
    }
    float4 bv0 = *(const float4*)&bias[n0 + tx*8];
    float4 bv1 = *(const float4*)&bias[n0 + tx*8 + 4];
    #pragma unroll
    for (int i = 0; i < 8; ++i) {
        float* d = &Cout[(size_t)(m0 + ty*8 + i)*1024 + n0 + tx*8];
        *(float4*)(d+0) = make_float4(acc[i][0]+bv0.x, acc[i][1]+bv0.y,
                                      acc[i][2]+bv0.z, acc[i][3]+bv0.w);
        *(float4*)(d+4) = make_float4(acc[i][4]+bv1.x, acc[i][5]+bv1.y,
                                      acc[i][6]+bv1.z, acc[i][7]+bv1.w);
    }
}

// ---------------------------------------------------------------------
// Gate GEMM: A = concat(x_chunk, ttt) [4096, 2048] @ Wg[2048,1024] + bg.
// ---------------------------------------------------------------------
__global__ void k_gemm_gate(const float* __restrict__ x, const float* __restrict__ Wg,
                            const float* __restrict__ bias, int t0) {
    __shared__ float As[8*132];
    __shared__ float Bs[8*128];
    const int m0 = blockIdx.y * 128, n0 = blockIdx.x * 128;
    const int tid = threadIdx.x, tx = tid & 15, ty = tid >> 4;
    float acc[8][8];
    #pragma unroll
    for (int i = 0; i < 8; ++i)
        #pragma unroll
        for (int j = 0; j < 8; ++j) acc[i][j] = 0.f;

    const int am = tid >> 1, ak = (tid & 1) * 4;
    const int bk = tid >> 5, bn = (tid & 31) * 4;
    const int mg = m0 + am, bb = mg >> 6, tt = mg & 63;
    const float* xrow = &x[((size_t)bb*SS + t0 + tt)*HH];
    const float* trow = &g_ttt[(size_t)mg*HH];

    for (int k0 = 0; k0 < 2048; k0 += 8) {
        int kk0 = k0 + ak;
        float4 a = (kk0 < 1024) ? *(const float4*)&xrow[kk0]
                                : *(const float4*)&trow[kk0 - 1024];
        As[(ak+0)*132+am]=a.x; As[(ak+1)*132+am]=a.y;
        As[(ak+2)*132+am]=a.z; As[(ak+3)*132+am]=a.w;
        *(float4*)&Bs[bk*128 + bn] = *(const float4*)&Wg[(size_t)(k0+bk)*1024 + n0 + bn];
        __syncthreads();
        #pragma unroll
        for (int kk = 0; kk < 8; ++kk) {
            float4 a0 = *(const float4*)&As[kk*132 + ty*8];
            float4 a1 = *(const float4*)&As[kk*132 + ty*8 + 4];
            float4 b0 = *(const float4*)&Bs[kk*128 + tx*8];
            float4 b1 = *(const float4*)&Bs[kk*128 + tx*8 + 4];
            float ar[8] = {a0.x,a0.y,a0.z,a0.w,a1.x,a1.y,a1.z,a1.w};
            float br[8] = {b0.x,b0.y,b0.z,b0.w,b1.x,b1.y,b1.z,b1.w};
            #pragma unroll
            for (int i = 0; i < 8; ++i)
                #pragma unroll
                for (int j = 0; j < 8; ++j) acc[i][j] += ar[i]*br[j];
        }
        __syncthreads();
    }
    float4 bv0 = *(const float4*)&bias[n0 + tx*8];
    float4 bv1 = *(const float4*)&bias[n0 + tx*8 + 4];
    #pragma unroll
    for (int i = 0; i < 8; ++i) {
        float* d = &g_gate[(size_t)(m0 + ty*8 + i)*1024 + n0 + tx*8];
        *(float4*)(d+0) = make_float4(acc[i][0]+bv0.x, acc[i][1]+bv0.y,
                                      acc[i][2]+bv0.z, acc[i][3]+bv0.w);
        *(float4*)(d+4) = make_float4(acc[i][4]+bv1.x, acc[i][5]+bv1.y,
                                      acc[i][6]+bv1.z, acc[i][7]+bv1.w);
    }
}

// ---------------------------------------------------------------------
// Epilogue: gate sigmoid, mix, LayerNorm, write out. One block per row.
// ---------------------------------------------------------------------
__global__ void k_epi(const float* __restrict__ x, const float* __restrict__ gamma,
                      const float* __restrict__ beta, float* __restrict__ out, int t0) {
    const int row = blockIdx.x;            // 0..4095
    const int b = row >> 6, t = row & 63;
    const int tid = threadIdx.x;           // 256
    const size_t xr = ((size_t)b*SS + t0 + t)*HH;
    float z[4], lsum = 0.f, lsq = 0.f;
    #pragma unroll
    for (int l = 0; l < 4; ++l) {
        int j = tid + l*256;
        float tv = g_ttt[(size_t)row*HH + j];
        float gv = g_gate[(size_t)row*HH + j];
        float gate = 1.0f / (1.0f + expf(-gv));
        float xv = x[xr + j];
        float zz = gate*tv + (1.0f - gate)*xv;
        z[l] = zz; lsum += zz; lsq += zz*zz;
    }
    __shared__ float s1[8], s2[8];
    #pragma unroll
    for (int off = 16; off > 0; off >>= 1) {
        lsum += __shfl_xor_sync(0xFFFFFFFFu, lsum, off);
        lsq  += __shfl_xor_sync(0xFFFFFFFFu, lsq,  off);
    }
    int lane = tid & 31, wid = tid >> 5;
    if (lane == 0) { s1[wid] = lsum; s2[wid] = lsq; }
    __syncthreads();
    if (wid == 0) {
        float v1 = (lane < 8) ? s1[lane] : 0.f;
        float v2 = (lane < 8) ? s2[lane] : 0.f;
        #pragma unroll
        for (int off = 4; off > 0; off >>= 1) {
            v1 += __shfl_xor_sync(0xFFFFFFFFu, v1, off);
            v2 += __shfl_xor_sync(0xFFFFFFFFu, v2, off);
        }
        if (lane == 0) { s1[0] = v1; s2[0] = v2; }
    }
    __syncthreads();
    float mu  = s1[0] * (1.0f / HH);
    float var = s2[0] * (1.0f / HH) - mu*mu;
    float inv = rsqrtf(var + EPSF);
    #pragma unroll
    for (int l = 0; l < 4; ++l) {
        int j = tid + l*256;
        out[xr + j] = (z[l] - mu) * inv * gamma[j] + beta[j];
    }
}

// ---------------------------------------------------------------------
extern "C" void kernel_launch(void* const* d_in, const int* in_sizes, int n_in,
                              void* d_out, int out_size) {
    const float* x      = (const float*)d_in[0];
    const float* W_init = (const float*)d_in[1];
    const float* b_init = (const float*)d_in[2];
    const float* Wt     = (const float*)d_in[3];
    const float* bt     = (const float*)d_in[4];
    const float* Wo     = (const float*)d_in[5];
    const float* bo     = (const float*)d_in[6];
    const float* Wg     = (const float*)d_in[7];
    const float* bg     = (const float*)d_in[8];
    const float* gamma  = (const float*)d_in[9];
    const float* beta   = (const float*)d_in[10];
    float* out = (float*)d_out;

    static int attr_done = 0;
    if (!attr_done) {
        cudaFuncSetAttribute(k_wpass, cudaFuncAttributeMaxDynamicSharedMemorySize, 66560);
        attr_done = 1;
    }

    float *p_act, *p_tgt, *p_ttt;
    cudaGetSymbolAddress((void**)&p_act, g_act);
    cudaGetSymbolAddress((void**)&p_tgt, g_tgt);
    cudaGetSymbolAddress((void**)&p_ttt, g_ttt);

    k_init<<<2048, 256>>>(W_init, b_init);
    // all targets in one GEMM: x[32768,1024] @ Wt[1024,1024] + bt
    k_gemm<<<dim3(8, 256), 256>>>(x, Wt, bt, p_tgt, 1024);

    for (int c = 0; c < NCH; ++c) {
        const int t0 = c * CC;
        k_gram<<<BB, 256>>>(x, t0);
        k_wpass<<<dim3(8, BB), 256, 66560>>>(x, t0, c > 0);
        k_recur<<<dim3(4, BB), 256>>>(t0);
        k_gemm<<<dim3(8, 32), 256>>>(p_act, Wo, bo, p_ttt, 1024);
        k_gemm_gate<<<dim3(8, 32), 256>>>(x, Wg, bg, t0);
        k_epi<<<BB*CC, 256>>>(x, gamma, beta, out, t0);
    }
}

// round 6
// speedup vs baseline: 1.2581x; 1.2581x over previous
#include <cuda_runtime.h>
#include <cuda_bf16.h>
#include <stdint.h>
#include <math.h>

#define BB 64
#define SS 512
#define HH 1024
#define II 1024
#define CC 64
#define NCH (SS/CC)
#define LRI (0.01f/1024.0f)
#define EPSF 1e-5f

typedef __nv_bfloat16 bf16;
typedef __nv_bfloat162 bf162;

// ---------------- device state (no allocation allowed) ----------------
__device__ float g_W[(size_t)BB*HH*II];    // 256 MB fast weights
__device__ float g_bst[BB*II];
__device__ float g_tgt[(size_t)BB*SS*II];  // targets
__device__ float g_xg[(size_t)BB*SS*HH];   // x @ Wg1 + bg
__device__ float g_base[BB*CC*II];
__device__ float g_err[BB*CC*II];
__device__ float g_ttt[BB*CC*HH];
__device__ float g_gate[BB*CC*HH];
__device__ float g_G[BB*CC*CC];
// bf16 split operands
__device__ bf16 g_xhi[(size_t)BB*SS*HH];
__device__ bf16 g_xlo[(size_t)BB*SS*HH];
__device__ bf16 g_acthi[BB*CC*II];
__device__ bf16 g_actlo[BB*CC*II];
__device__ bf16 g_ttthi[BB*CC*HH];
__device__ bf16 g_tttlo[BB*CC*HH];
// transposed split weights [N,K]
__device__ bf16 g_WtThi[HH*II];
__device__ bf16 g_WtTlo[HH*II];
__device__ bf16 g_WoThi[II*HH];
__device__ bf16 g_WoTlo[II*HH];
__device__ bf16 g_Wg1Thi[HH*HH];
__device__ bf16 g_Wg1Tlo[HH*HH];
__device__ bf16 g_Wg2Thi[HH*HH];
__device__ bf16 g_Wg2Tlo[HH*HH];

// ---------------------------------------------------------------------
__global__ void k_init(const float* __restrict__ Wi, const float* __restrict__ bi) {
    size_t stride = (size_t)gridDim.x * blockDim.x;
    size_t t0 = (size_t)blockIdx.x * blockDim.x + threadIdx.x;
    const size_t NW = (size_t)BB * HH * II;
    for (size_t i = t0; i < NW; i += stride) g_W[i] = Wi[i & (HH*II - 1)];
    for (size_t i = t0; i < (size_t)BB*II; i += stride) g_bst[i] = bi[i & (II - 1)];
}

// split x into hi/lo bf16
__global__ void k_split_x(const float* __restrict__ x) {
    size_t stride = (size_t)gridDim.x * blockDim.x;
    size_t i0 = (size_t)blockIdx.x * blockDim.x + threadIdx.x;
    const size_t N4 = (size_t)BB*SS*HH/4;
    bf162* xhi2 = (bf162*)g_xhi;
    bf162* xlo2 = (bf162*)g_xlo;
    for (size_t i = i0; i < N4; i += stride) {
        float4 v = ((const float4*)x)[i];
        bf16 h0 = __float2bfloat16_rn(v.x), h1 = __float2bfloat16_rn(v.y);
        bf16 h2 = __float2bfloat16_rn(v.z), h3 = __float2bfloat16_rn(v.w);
        bf16 l0 = __float2bfloat16_rn(v.x - __bfloat162float(h0));
        bf16 l1 = __float2bfloat16_rn(v.y - __bfloat162float(h1));
        bf16 l2 = __float2bfloat16_rn(v.z - __bfloat162float(h2));
        bf16 l3 = __float2bfloat16_rn(v.w - __bfloat162float(h3));
        xhi2[2*i+0] = __halves2bfloat162(h0, h1);
        xhi2[2*i+1] = __halves2bfloat162(h2, h3);
        xlo2[2*i+0] = __halves2bfloat162(l0, l1);
        xlo2[2*i+1] = __halves2bfloat162(l2, l3);
    }
}

// transpose + split a 1024x1024 fp32 [K,N] into bf16 hi/lo [N,K]
// which: 0=WtT 1=WoT 2=Wg1T 3=Wg2T
__global__ void k_wconv(const float* __restrict__ W, int which) {
    bf16* Thi; bf16* Tlo;
    if      (which == 0) { Thi = g_WtThi;  Tlo = g_WtTlo;  }
    else if (which == 1) { Thi = g_WoThi;  Tlo = g_WoTlo;  }
    else if (which == 2) { Thi = g_Wg1Thi; Tlo = g_Wg1Tlo; }
    else                 { Thi = g_Wg2Thi; Tlo = g_Wg2Tlo; }
    __shared__ float ts[32][33];
    const int k0 = blockIdx.y*32, n0 = blockIdx.x*32;
    const int tid = threadIdx.x;
    const int rr = tid >> 5, cc = tid & 31;
    #pragma unroll
    for (int i = 0; i < 4; ++i)
        ts[rr + i*8][cc] = W[(size_t)(k0 + rr + i*8)*1024 + n0 + cc];
    __syncthreads();
    #pragma unroll
    for (int i = 0; i < 4; ++i) {
        int nrow = rr + i*8, kcol = cc;
        float v = ts[kcol][nrow];
        bf16 h = __float2bfloat16_rn(v);
        Thi[(size_t)(n0 + nrow)*1024 + k0 + kcol] = h;
        Tlo[(size_t)(n0 + nrow)*1024 + k0 + kcol] =
            __float2bfloat16_rn(v - __bfloat162float(h));
    }
}

// ---------------------------------------------------------------------
// Gram: G[b][t][s] = x_{t0+t} . x_{t0+s}
// ---------------------------------------------------------------------
__global__ void k_gram(const float* __restrict__ x, int t0) {
    const int b = blockIdx.x, tid = threadIdx.x;
    const int tq = tid >> 4, tr = tid & 15;
    __shared__ float Xs[64][33];
    float acc[4][4];
    #pragma unroll
    for (int i = 0; i < 4; ++i)
        #pragma unroll
        for (int j = 0; j < 4; ++j) acc[i][j] = 0.f;
    for (int h0 = 0; h0 < HH; h0 += 32) {
        int r = tid >> 2, c = (tid & 3) * 8;
        const float* xr = &x[((size_t)b*SS + t0 + r)*HH + h0 + c];
        float4 v0 = *(const float4*)xr, v1 = *(const float4*)(xr + 4);
        Xs[r][c+0]=v0.x; Xs[r][c+1]=v0.y; Xs[r][c+2]=v0.z; Xs[r][c+3]=v0.w;
        Xs[r][c+4]=v1.x; Xs[r][c+5]=v1.y; Xs[r][c+6]=v1.z; Xs[r][c+7]=v1.w;
        __syncthreads();
        #pragma unroll 8
        for (int h = 0; h < 32; ++h) {
            float a0=Xs[tq*4+0][h], a1=Xs[tq*4+1][h], a2=Xs[tq*4+2][h], a3=Xs[tq*4+3][h];
            float b0=Xs[tr*4+0][h], b1=Xs[tr*4+1][h], b2=Xs[tr*4+2][h], b3=Xs[tr*4+3][h];
            acc[0][0]+=a0*b0; acc[0][1]+=a0*b1; acc[0][2]+=a0*b2; acc[0][3]+=a0*b3;
            acc[1][0]+=a1*b0; acc[1][1]+=a1*b1; acc[1][2]+=a1*b2; acc[1][3]+=a1*b3;
            acc[2][0]+=a2*b0; acc[2][1]+=a2*b1; acc[2][2]+=a2*b2; acc[2][3]+=a2*b3;
            acc[3][0]+=a3*b0; acc[3][1]+=a3*b1; acc[3][2]+=a3*b2; acc[3][3]+=a3*b3;
        }
        __syncthreads();
    }
    #pragma unroll
    for (int i = 0; i < 4; ++i)
        #pragma unroll
        for (int j = 0; j < 4; ++j)
            g_G[(b*CC + tq*4+i)*CC + tr*4+j] = acc[i][j];
}

// ---------------------------------------------------------------------
// Fused W pass
// ---------------------------------------------------------------------
__global__ void k_wpass(const float* __restrict__ x, int t0, int do_update) {
    extern __shared__ float sm[];
    float* Ep = sm;
    float* Xp = Ep + 64*128;
    float* Xc = Xp + 64*33;
    float* Wt = Xc + 64*33;
    const int b = blockIdx.y, i0 = blockIdx.x * 128, tid = threadIdx.x;
    const int uh = tid >> 3, ui = (tid & 7) * 16;
    const int tm = tid >> 4, tn = tid & 15;

    if (do_update) {
        #pragma unroll
        for (int l = 0; l < 8; ++l) {
            int fl = tid + l*256;
            int s = fl >> 5, ii = (fl & 31) * 4;
            float4 e = *(const float4*)&g_err[((b<<6)+s)*II + i0 + ii];
            float* d = &Ep[s*128 + ii];
            d[0]=LRI*e.x; d[1]=LRI*e.y; d[2]=LRI*e.z; d[3]=LRI*e.w;
        }
    }
    float acc[4][8];
    #pragma unroll
    for (int i = 0; i < 4; ++i)
        #pragma unroll
        for (int j = 0; j < 8; ++j) acc[i][j] = 0.f;

    for (int h0 = 0; h0 < HH; h0 += 32) {
        {
            int r = tid >> 2, c = (tid & 3) * 8;
            const float* xr = &x[((size_t)b*SS + t0 + r)*HH + h0 + c];
            float4 v0 = *(const float4*)xr, v1 = *(const float4*)(xr+4);
            float* d = &Xc[r*33 + c];
            d[0]=v0.x; d[1]=v0.y; d[2]=v0.z; d[3]=v0.w;
            d[4]=v1.x; d[5]=v1.y; d[6]=v1.z; d[7]=v1.w;
            if (do_update) {
                const float* xpr = xr - (size_t)CC*HH;
                float4 p0 = *(const float4*)xpr, p1 = *(const float4*)(xpr+4);
                float* dp = &Xp[r*33 + c];
                dp[0]=p0.x; dp[1]=p0.y; dp[2]=p0.z; dp[3]=p0.w;
                dp[4]=p1.x; dp[5]=p1.y; dp[6]=p1.z; dp[7]=p1.w;
            }
        }
        float* wg = &g_W[(((size_t)b<<10) + (h0 + uh))*II + i0 + ui];
        float4 w0 = *(float4*)(wg+0), w1 = *(float4*)(wg+4);
        float4 w2 = *(float4*)(wg+8), w3 = *(float4*)(wg+12);
        __syncthreads();
        if (do_update) {
            #pragma unroll 4
            for (int s = 0; s < 64; ++s) {
                float xv = Xp[s*33 + uh];
                const float* e = &Ep[s*128 + ui];
                float4 e0 = *(const float4*)(e+0), e1 = *(const float4*)(e+4);
                float4 e2 = *(const float4*)(e+8), e3 = *(const float4*)(e+12);
                w0.x-=xv*e0.x; w0.y-=xv*e0.y; w0.z-=xv*e0.z; w0.w-=xv*e0.w;
                w1.x-=xv*e1.x; w1.y-=xv*e1.y; w1.z-=xv*e1.z; w1.w-=xv*e1.w;
                w2.x-=xv*e2.x; w2.y-=xv*e2.y; w2.z-=xv*e2.z; w2.w-=xv*e2.w;
                w3.x-=xv*e3.x; w3.y-=xv*e3.y; w3.z-=xv*e3.z; w3.w-=xv*e3.w;
            }
            *(float4*)(wg+0)=w0; *(float4*)(wg+4)=w1;
            *(float4*)(wg+8)=w2; *(float4*)(wg+12)=w3;
        }
        {
            float* d = &Wt[uh*132 + ui];
            *(float4*)(d+0)=w0; *(float4*)(d+4)=w1;
            *(float4*)(d+8)=w2; *(float4*)(d+12)=w3;
        }
        __syncthreads();
        #pragma unroll 4
        for (int h = 0; h < 32; ++h) {
            float a0 = Xc[(tm*4+0)*33 + h], a1 = Xc[(tm*4+1)*33 + h];
            float a2 = Xc[(tm*4+2)*33 + h], a3 = Xc[(tm*4+3)*33 + h];
            const float* wr = &Wt[h*132 + tn*8];
            float4 b0 = *(const float4*)(wr+0), b1 = *(const float4*)(wr+4);
            acc[0][0]+=a0*b0.x; acc[0][1]+=a0*b0.y; acc[0][2]+=a0*b0.z; acc[0][3]+=a0*b0.w;
            acc[0][4]+=a0*b1.x; acc[0][5]+=a0*b1.y; acc[0][6]+=a0*b1.z; acc[0][7]+=a0*b1.w;
            acc[1][0]+=a1*b0.x; acc[1][1]+=a1*b0.y; acc[1][2]+=a1*b0.z; acc[1][3]+=a1*b0.w;
            acc[1][4]+=a1*b1.x; acc[1][5]+=a1*b1.y; acc[1][6]+=a1*b1.z; acc[1][7]+=a1*b1.w;
            acc[2][0]+=a2*b0.x; acc[2][1]+=a2*b0.y; acc[2][2]+=a2*b0.z; acc[2][3]+=a2*b0.w;
            acc[2][4]+=a2*b1.x; acc[2][5]+=a2*b1.y; acc[2][6]+=a2*b1.z; acc[2][7]+=a2*b1.w;
            acc[3][0]+=a3*b0.x; acc[3][1]+=a3*b0.y; acc[3][2]+=a3*b0.z; acc[3][3]+=a3*b0.w;
            acc[3][4]+=a3*b1.x; acc[3][5]+=a3*b1.y; acc[3][6]+=a3*b1.z; acc[3][7]+=a3*b1.w;
        }
        __syncthreads();
    }
    #pragma unroll
    for (int si = 0; si < 4; ++si) {
        float* d = &g_base[((b<<6) + tm*4 + si)*II + i0 + tn*8];
        *(float4*)(d+0) = make_float4(acc[si][0],acc[si][1],acc[si][2],acc[si][3]);
        *(float4*)(d+4) = make_float4(acc[si][4],acc[si][5],acc[si][6],acc[si][7]);
    }
}

// ---------------------------------------------------------------------
// Recurrence: emits err + bf16 hi/lo of silu(inner)
// ---------------------------------------------------------------------
__global__ void k_recur(int t0) {
    __shared__ float Gs[CC*CC];
    const int b = blockIdx.y;
    const int i = blockIdx.x * 256 + threadIdx.x;
    const int tid = threadIdx.x;
    #pragma unroll
    for (int l = 0; l < 16; ++l)
        Gs[tid + l*256] = LRI * (g_G[b*CC*CC + tid + l*256] + 1.0f);
    __syncthreads();

    float bstv = g_bst[b*II + i];
    float eh[CC];
    float sumerr = 0.f;
    #pragma unroll
    for (int t = 0; t < CC; ++t) {
        float inner = g_base[((b<<6)+t)*II + i] + bstv;
        #pragma unroll
        for (int s = 0; s < t; ++s) inner -= Gs[t*CC + s] * eh[s];
        float tg = g_tgt[((size_t)b*SS + t0 + t)*II + i];
        float e = inner - tg;
        eh[t] = e; sumerr += e;
        int idx = ((b<<6)+t)*II + i;
        g_err[idx] = e;
        float a = inner / (1.0f + expf(-inner));
        bf16 h = __float2bfloat16_rn(a);
        g_acthi[idx] = h;
        g_actlo[idx] = __float2bfloat16_rn(a - __bfloat162float(h));
    }
    g_bst[b*II + i] = bstv - LRI * sumerr;
}

// ---------------------------------------------------------------------
// Tensor-core bf16x3 GEMM. Operands selected by op (device-side; no host
// symbol plumbing). op: 0=targets 1=xg 2=ttt(+split out) 3=gate(+xg add)
// ---------------------------------------------------------------------
__device__ __forceinline__ void cpa16(uint32_t s, const void* g) {
    asm volatile("cp.async.cg.shared.global [%0], [%1], 16;" :: "r"(s), "l"(g));
}
__device__ __forceinline__ void ldm4(uint32_t& r0, uint32_t& r1, uint32_t& r2,
                                     uint32_t& r3, uint32_t a) {
    asm volatile("ldmatrix.sync.aligned.m8n8.x4.shared.b16 {%0,%1,%2,%3},[%4];"
                 : "=r"(r0),"=r"(r1),"=r"(r2),"=r"(r3) : "r"(a));
}
__device__ __forceinline__ void ldm2(uint32_t& r0, uint32_t& r1, uint32_t a) {
    asm volatile("ldmatrix.sync.aligned.m8n8.x2.shared.b16 {%0,%1},[%2];"
                 : "=r"(r0),"=r"(r1) : "r"(a));
}
__device__ __forceinline__ void mma16816(float* c, const uint32_t* a, const uint32_t* b) {
    asm volatile("mma.sync.aligned.m16n8k16.row.col.f32.bf16.bf16.f32 "
                 "{%0,%1,%2,%3},{%4,%5,%6,%7},{%8,%9},{%0,%1,%2,%3};"
                 : "+f"(c[0]),"+f"(c[1]),"+f"(c[2]),"+f"(c[3])
                 : "r"(a[0]),"r"(a[1]),"r"(a[2]),"r"(a[3]),"r"(b[0]),"r"(b[1]));
}

#define TSTAGE 40960      // bytes per stage: 4 tiles of 128x40 bf16

__global__ void __launch_bounds__(256)
k_tmma(int op, const float* __restrict__ bias, int t0) {
    const bf16 *Ahi, *Alo, *Bhi, *Blo;
    float* Cout;
    bf16* Chi = 0; bf16* Clo = 0;
    const float* xgp = 0;
    if (op == 0)      { Ahi=g_xhi;   Alo=g_xlo;   Bhi=g_WtThi;  Blo=g_WtTlo;  Cout=g_tgt; }
    else if (op == 1) { Ahi=g_xhi;   Alo=g_xlo;   Bhi=g_Wg1Thi; Blo=g_Wg1Tlo; Cout=g_xg; }
    else if (op == 2) { Ahi=g_acthi; Alo=g_actlo; Bhi=g_WoThi;  Blo=g_WoTlo;  Cout=g_ttt;
                        Chi=g_ttthi; Clo=g_tttlo; }
    else              { Ahi=g_ttthi; Alo=g_tttlo; Bhi=g_Wg2Thi; Blo=g_Wg2Tlo; Cout=g_gate;
                        xgp=g_xg; }

    extern __shared__ __align__(16) char smc[];
    const uint32_t smBase = (uint32_t)__cvta_generic_to_shared(smc);
    const int tid = threadIdx.x;
    const int lane = tid & 31, w = tid >> 5;
    const int wm = w & 1, wn = w >> 1;
    const int m0 = blockIdx.y * 128, n0 = blockIdx.x * 128;

    float acc[4][4][4];
    #pragma unroll
    for (int i = 0; i < 4; ++i)
        #pragma unroll
        for (int j = 0; j < 4; ++j)
            #pragma unroll
            for (int k = 0; k < 4; ++k) acc[i][j][k] = 0.f;

    const int r0w = tid >> 2,         k0w = (tid & 3) * 8;
    const int r1w = (tid + 256) >> 2, k1w = k0w;
    const uint32_t so0 = (uint32_t)(r0w*80 + k0w*2);
    const uint32_t so1 = (uint32_t)(r1w*80 + k1w*2);

    const bf16* gAhi = Ahi + (size_t)m0*1024;
    const bf16* gAlo = Alo + (size_t)m0*1024;
    const bf16* gBhi = Bhi + (size_t)n0*1024;
    const bf16* gBlo = Blo + (size_t)n0*1024;
    const size_t go0 = (size_t)r0w*1024 + k0w;
    const size_t go1 = (size_t)r1w*1024 + k1w;

    const int aoff = (wm*64 + (lane & 15))*40 + (lane >> 4)*8;
    const int boff = (wn*32 + (lane & 7))*40 + ((lane >> 3) & 1)*8;

    {   // prologue
        uint32_t s = smBase;
        cpa16(s +         so0, gAhi + go0); cpa16(s +         so1, gAhi + go1);
        cpa16(s + 10240 + so0, gAlo + go0); cpa16(s + 10240 + so1, gAlo + go1);
        cpa16(s + 20480 + so0, gBhi + go0); cpa16(s + 20480 + so1, gBhi + go1);
        cpa16(s + 30720 + so0, gBlo + go0); cpa16(s + 30720 + so1, gBlo + go1);
        asm volatile("cp.async.commit_group;");
        asm volatile("cp.async.wait_group 0;");
    }
    __syncthreads();

    for (int it = 0; it < 32; ++it) {
        const int cur = it & 1;
        if (it < 31) {
            const int kk = (it + 1) * 32;
            uint32_t s = smBase + (cur ^ 1) * TSTAGE;
            cpa16(s +         so0, gAhi + kk + go0); cpa16(s +         so1, gAhi + kk + go1);
            cpa16(s + 10240 + so0, gAlo + kk + go0); cpa16(s + 10240 + so1, gAlo + kk + go1);
            cpa16(s + 20480 + so0, gBhi + kk + go0); cpa16(s + 20480 + so1, gBhi + kk + go1);
            cpa16(s + 30720 + so0, gBlo + kk + go0); cpa16(s + 30720 + so1, gBlo + kk + go1);
            asm volatile("cp.async.commit_group;");
        }
        const uint32_t sb = smBase + cur * TSTAGE;
        #pragma unroll
        for (int ks = 0; ks < 2; ++ks) {
            uint32_t ah[4][4], al[4][4], bh[4][2], bl[4][2];
            #pragma unroll
            for (int mi = 0; mi < 4; ++mi) {
                uint32_t a = sb + 2*(aoff + mi*640 + ks*16);
                ldm4(ah[mi][0], ah[mi][1], ah[mi][2], ah[mi][3], a);
                ldm4(al[mi][0], al[mi][1], al[mi][2], al[mi][3], a + 10240);
            }
            #pragma unroll
            for (int ni = 0; ni < 4; ++ni) {
                uint32_t a = sb + 20480 + 2*(boff + ni*320 + ks*16);
                ldm2(bh[ni][0], bh[ni][1], a);
                ldm2(bl[ni][0], bl[ni][1], a + 10240);
            }
            #pragma unroll
            for (int mi = 0; mi < 4; ++mi)
                #pragma unroll
                for (int ni = 0; ni < 4; ++ni) {
                    mma16816(acc[mi][ni], ah[mi], bh[ni]);
                    mma16816(acc[mi][ni], ah[mi], bl[ni]);
                    mma16816(acc[mi][ni], al[mi], bh[ni]);
                }
        }
        if (it < 31) asm volatile("cp.async.wait_group 0;");
        __syncthreads();
    }

    // epilogue
    #pragma unroll
    for (int mi = 0; mi < 4; ++mi) {
        #pragma unroll
        for (int ni = 0; ni < 4; ++ni) {
            int r = m0 + wm*64 + mi*16 + (lane >> 2);
            int cc = n0 + wn*32 + ni*8 + 2*(lane & 3);
            float v0 = acc[mi][ni][0], v1 = acc[mi][ni][1];
            float v2 = acc[mi][ni][2], v3 = acc[mi][ni][3];
            if (op == 3) {
                size_t gr0 = ((size_t)(r>>6)*SS + t0 + (r&63))*1024 + cc;
                size_t gr1 = ((size_t)((r+8)>>6)*SS + t0 + ((r+8)&63))*1024 + cc;
                float2 x0 = *(const float2*)&xgp[gr0];
                float2 x1 = *(const float2*)&xgp[gr1];
                v0 += x0.x; v1 += x0.y; v2 += x1.x; v3 += x1.y;
            } else {
                float2 bv = *(const float2*)&bias[cc];
                v0 += bv.x; v1 += bv.y; v2 += bv.x; v3 += bv.y;
            }
            *(float2*)&Cout[(size_t)r*1024 + cc]     = make_float2(v0, v1);
            *(float2*)&Cout[(size_t)(r+8)*1024 + cc] = make_float2(v2, v3);
            if (op == 2) {
                bf16 h0 = __float2bfloat16_rn(v0), h1 = __float2bfloat16_rn(v1);
                bf16 h2 = __float2bfloat16_rn(v2), h3 = __float2bfloat16_rn(v3);
                *(bf162*)&Chi[(size_t)r*1024 + cc]     = __halves2bfloat162(h0, h1);
                *(bf162*)&Chi[(size_t)(r+8)*1024 + cc] = __halves2bfloat162(h2, h3);
                *(bf162*)&Clo[(size_t)r*1024 + cc] = __halves2bfloat162(
                    __float2bfloat16_rn(v0 - __bfloat162float(h0)),
                    __float2bfloat16_rn(v1 - __bfloat162float(h1)));
                *(bf162*)&Clo[(size_t)(r+8)*1024 + cc] = __halves2bfloat162(
                    __float2bfloat16_rn(v2 - __bfloat162float(h2)),
                    __float2bfloat16_rn(v3 - __bfloat162float(h3)));
            }
        }
    }
}

// ---------------------------------------------------------------------
// Epilogue: gate sigmoid, mix, LayerNorm, write out.
// ---------------------------------------------------------------------
__global__ void k_epi(const float* __restrict__ x, const float* __restrict__ gamma,
                      const float* __restrict__ beta, float* __restrict__ out, int t0) {
    const int row = blockIdx.x;
    const int b = row >> 6, t = row & 63;
    const int tid = threadIdx.x;
    const size_t xr = ((size_t)b*SS + t0 + t)*HH;
    float z[4], lsum = 0.f, lsq = 0.f;
    #pragma unroll
    for (int l = 0; l < 4; ++l) {
        int j = tid + l*256;
        float tv = g_ttt[(size_t)row*HH + j];
        float gv = g_gate[(size_t)row*HH + j];
        float gate = 1.0f / (1.0f + expf(-gv));
        float xv = x[xr + j];
        float zz = gate*tv + (1.0f - gate)*xv;
        z[l] = zz; lsum += zz; lsq += zz*zz;
    }
    __shared__ float s1[8], s2[8];
    #pragma unroll
    for (int off = 16; off > 0; off >>= 1) {
        lsum += __shfl_xor_sync(0xFFFFFFFFu, lsum, off);
        lsq  += __shfl_xor_sync(0xFFFFFFFFu, lsq,  off);
    }
    int lane = tid & 31, wid = tid >> 5;
    if (lane == 0) { s1[wid] = lsum; s2[wid] = lsq; }
    __syncthreads();
    if (wid == 0) {
        float v1 = (lane < 8) ? s1[lane] : 0.f;
        float v2 = (lane < 8) ? s2[lane] : 0.f;
        #pragma unroll
        for (int off = 4; off > 0; off >>= 1) {
            v1 += __shfl_xor_sync(0xFFFFFFFFu, v1, off);
            v2 += __shfl_xor_sync(0xFFFFFFFFu, v2, off);
        }
        if (lane == 0) { s1[0] = v1; s2[0] = v2; }
    }
    __syncthreads();
    float mu  = s1[0] * (1.0f / HH);
    float var = s2[0] * (1.0f / HH) - mu*mu;
    float inv = rsqrtf(var + EPSF);
    #pragma unroll
    for (int l = 0; l < 4; ++l) {
        int j = tid + l*256;
        out[xr + j] = (z[l] - mu) * inv * gamma[j] + beta[j];
    }
}

// ---------------------------------------------------------------------
extern "C" void kernel_launch(void* const* d_in, const int* in_sizes, int n_in,
                              void* d_out, int out_size) {
    const float* x      = (const float*)d_in[0];
    const float* W_init = (const float*)d_in[1];
    const float* b_init = (const float*)d_in[2];
    const float* bt     = (const float*)d_in[4];
    const float* Wt     = (const float*)d_in[3];
    const float* Wo     = (const float*)d_in[5];
    const float* bo     = (const float*)d_in[6];
    const float* Wg     = (const float*)d_in[7];
    const float* bg     = (const float*)d_in[8];
    const float* gamma  = (const float*)d_in[9];
    const float* beta   = (const float*)d_in[10];
    float* out = (float*)d_out;

    static int attr_done = 0;
    if (!attr_done) {
        cudaFuncSetAttribute(k_wpass, cudaFuncAttributeMaxDynamicSharedMemorySize, 66560);
        cudaFuncSetAttribute(k_tmma, cudaFuncAttributeMaxDynamicSharedMemorySize, 2*TSTAGE);
        attr_done = 1;
    }

    k_init<<<2048, 256>>>(W_init, b_init);
    k_split_x<<<2048, 256>>>(x);
    k_wconv<<<dim3(32,32), 256>>>(Wt, 0);
    k_wconv<<<dim3(32,32), 256>>>(Wo, 1);
    k_wconv<<<dim3(32,32), 256>>>(Wg, 2);
    k_wconv<<<dim3(32,32), 256>>>(Wg + 1024*1024, 3);

    // big upfront GEMMs: targets and x-side of the gate
    k_tmma<<<dim3(8,256), 256, 2*TSTAGE>>>(0, bt, 0);
    k_tmma<<<dim3(8,256), 256, 2*TSTAGE>>>(1, bg, 0);

    for (int c = 0; c < NCH; ++c) {
        const int t0 = c * CC;
        k_gram<<<BB, 256>>>(x, t0);
        k_wpass<<<dim3(8, BB), 256, 66560>>>(x, t0, c > 0);
        k_recur<<<dim3(4, BB), 256>>>(t0);
        k_tmma<<<dim3(8,32), 256, 2*TSTAGE>>>(2, bo, 0);
        k_tmma<<<dim3(8,32), 256, 2*TSTAGE>>>(3, bt, t0);
        k_epi<<<BB*CC, 256>>>(x, gamma, beta, out, t0);
    }
}